// round 5
// baseline (speedup 1.0000x reference)
#include <cuda_runtime.h>
#include <cuda_bf16.h>
#include <cstdint>

#define NMAX 50000
#define EMAX 800000
#define DIMH 128
#define NHEADS 8
#define HEADDIM 16

// ---------------------------------------------------------------------------
// Scratch
// ---------------------------------------------------------------------------
__device__ float g_Q[(size_t)NMAX * DIMH];
__device__ float g_K[(size_t)NMAX * DIMH];
__device__ float g_V[(size_t)NMAX * DIMH];
__device__ float g_ex[(size_t)EMAX * NHEADS];   // exp(score), CSR-ordered
__device__ int   g_ssrc[EMAX];                  // src, CSR-ordered
__device__ int   g_seid[EMAX];                  // original edge id, CSR-ordered
__device__ int   g_count[NMAX];
__device__ int   g_off[NMAX + 1];
__device__ int   g_cur[NMAX];

// ---------------------------------------------------------------------------
// Helpers
// ---------------------------------------------------------------------------
__device__ __forceinline__ void red_add_u32(int* addr, unsigned v) {
    asm volatile("red.global.add.u32 [%0], %1;" :: "l"(addr), "r"(v) : "memory");
}
__device__ __forceinline__ uint32_t f32_to_tf32(float f) {
    uint32_t r;
    asm("cvt.rna.tf32.f32 %0, %1;" : "=r"(r) : "f"(f));
    return r;
}
__device__ __forceinline__ void mma_tf32(float (&c)[4],
                                         uint32_t a0, uint32_t a1,
                                         uint32_t a2, uint32_t a3,
                                         uint32_t b0, uint32_t b1) {
    asm volatile("mma.sync.aligned.m16n8k8.row.col.f32.tf32.tf32.f32 "
                 "{%0,%1,%2,%3}, {%4,%5,%6,%7}, {%8,%9}, {%0,%1,%2,%3};"
                 : "+f"(c[0]), "+f"(c[1]), "+f"(c[2]), "+f"(c[3])
                 : "r"(a0), "r"(a1), "r"(a2), "r"(a3), "r"(b0), "r"(b1));
}

// ---------------------------------------------------------------------------
// Sort kernels: counting sort of edges by dst -> CSR
// ---------------------------------------------------------------------------
__global__ void k_zero_counts(int n) {
    int i = blockIdx.x * blockDim.x + threadIdx.x;
    if (i < n) g_count[i] = 0;
}

__global__ void k_hist(const int* __restrict__ ei, int E_) {
    int e = blockIdx.x * blockDim.x + threadIdx.x;
    if (e >= E_) return;
    int dst = __ldg(ei + E_ + e);
    red_add_u32(g_count + dst, 1u);
}

// Single-block exclusive scan over n counters -> g_off, g_cur
__global__ __launch_bounds__(1024)
void k_scan(int n) {
    __shared__ int sums[1024];
    int t = threadIdx.x;
    int chunk = (n + 1023) >> 10;
    int lo = t * chunk;
    int hi = min(lo + chunk, n);

    int s = 0;
    for (int i = lo; i < hi; i++) s += g_count[i];
    sums[t] = s;
    __syncthreads();

    // Hillis-Steele inclusive scan
    for (int off = 1; off < 1024; off <<= 1) {
        int v = 0;
        if (t >= off) v = sums[t - off];
        __syncthreads();
        if (t >= off) sums[t] += v;
        __syncthreads();
    }

    int run = (t > 0) ? sums[t - 1] : 0;   // exclusive prefix of this chunk
    for (int i = lo; i < hi; i++) {
        int c = g_count[i];
        g_off[i] = run;
        g_cur[i] = run;
        run += c;
    }
    if (t == 1023) g_off[n] = run;         // == E
}

__global__ void k_scatter(const int* __restrict__ ei, int E_) {
    int e = blockIdx.x * blockDim.x + threadIdx.x;
    if (e >= E_) return;
    int src = __ldg(ei + e);
    int dst = __ldg(ei + E_ + e);
    int pos = atomicAdd(g_cur + dst, 1);
    g_ssrc[pos] = src;
    g_seid[pos] = e;
}

// ---------------------------------------------------------------------------
// GEMM: tf32 mma.sync.  out = x @ W^T + b.  (unchanged from R4)
// ---------------------------------------------------------------------------
#define BK 32
#define SPAD 36

__global__ __launch_bounds__(256)
void gemm_qkv_mma(const float* __restrict__ x,
                  const float* __restrict__ WQ, const float* __restrict__ bQ,
                  const float* __restrict__ WK, const float* __restrict__ bK,
                  const float* __restrict__ WV, const float* __restrict__ bV,
                  int n) {
    const float* W;
    const float* bias;
    float* out;
    if (blockIdx.y == 0)      { W = WQ; bias = bQ; out = g_Q; }
    else if (blockIdx.y == 1) { W = WK; bias = bK; out = g_K; }
    else                      { W = WV; bias = bV; out = g_V; }

    __shared__ uint32_t As[128][SPAD];
    __shared__ uint32_t Bs[128][SPAD];

    const int tid  = threadIdx.x;
    const int wid  = tid >> 5;
    const int lane = tid & 31;
    const int g    = lane >> 2;
    const int t    = lane & 3;
    const int row0 = blockIdx.x * 128;
    const int mrow = wid * 16;

    float acc[16][4];
#pragma unroll
    for (int nt = 0; nt < 16; nt++)
#pragma unroll
        for (int j = 0; j < 4; j++) acc[nt][j] = 0.0f;

    for (int kc = 0; kc < DIMH; kc += BK) {
#pragma unroll
        for (int i = 0; i < 4; i++) {
            int idx = tid + i * 256;
            int row = idx >> 3;
            int c4  = idx & 7;
            int gr  = row0 + row;
            float4 a = make_float4(0.f, 0.f, 0.f, 0.f);
            if (gr < n) a = *(const float4*)(x + (size_t)gr * DIMH + kc + c4 * 4);
            As[row][c4 * 4 + 0] = f32_to_tf32(a.x);
            As[row][c4 * 4 + 1] = f32_to_tf32(a.y);
            As[row][c4 * 4 + 2] = f32_to_tf32(a.z);
            As[row][c4 * 4 + 3] = f32_to_tf32(a.w);

            float4 w = *(const float4*)(W + (size_t)row * DIMH + kc + c4 * 4);
            Bs[row][c4 * 4 + 0] = f32_to_tf32(w.x);
            Bs[row][c4 * 4 + 1] = f32_to_tf32(w.y);
            Bs[row][c4 * 4 + 2] = f32_to_tf32(w.z);
            Bs[row][c4 * 4 + 3] = f32_to_tf32(w.w);
        }
        __syncthreads();

#pragma unroll
        for (int ks = 0; ks < BK / 8; ks++) {
            int k0 = ks * 8;
            uint32_t a0 = As[mrow + g][k0 + t];
            uint32_t a1 = As[mrow + g + 8][k0 + t];
            uint32_t a2 = As[mrow + g][k0 + t + 4];
            uint32_t a3 = As[mrow + g + 8][k0 + t + 4];
#pragma unroll
            for (int nt = 0; nt < 16; nt++) {
                uint32_t b0 = Bs[nt * 8 + g][k0 + t];
                uint32_t b1 = Bs[nt * 8 + g][k0 + t + 4];
                mma_tf32(acc[nt], a0, a1, a2, a3, b0, b1);
            }
        }
        __syncthreads();
    }

    int r0 = row0 + mrow + g;
    int r1 = r0 + 8;
#pragma unroll
    for (int nt = 0; nt < 16; nt++) {
        int c = nt * 8 + 2 * t;
        float bx = __ldg(bias + c), by = __ldg(bias + c + 1);
        if (r0 < n) {
            float2 v0 = make_float2(acc[nt][0] + bx, acc[nt][1] + by);
            *(float2*)(out + (size_t)r0 * DIMH + c) = v0;
        }
        if (r1 < n) {
            float2 v1 = make_float2(acc[nt][2] + bx, acc[nt][3] + by);
            *(float2*)(out + (size_t)r1 * DIMH + c) = v1;
        }
    }
}

// ---------------------------------------------------------------------------
// CSR edge kernel: ONE WARP PER DESTINATION NODE.
// Loop 1: for each incoming edge, dot(Q[dst],K[src]) per head, ex=exp,
//         accumulate softmax denominator in registers, stash ex in g_ex.
// Loop 2: alpha = ex/denom; accumulate alpha*V[src] in registers;
//         write alpha to out_alpha[eid]; finally store out_h[dst] directly.
// No global reductions, no separate init/normalize/alpha kernels.
// ---------------------------------------------------------------------------
__global__ __launch_bounds__(256)
void csr_edge(const float* __restrict__ ebias,
              int n,
              float* __restrict__ out_h,
              float* __restrict__ out_alpha) {
    int d    = (blockIdx.x * blockDim.x + threadIdx.x) >> 5;
    int lane = threadIdx.x & 31;
    if (d >= n) return;

    int beg = g_off[d];
    int end = g_off[d + 1];

    // Q[dst] resident in registers: lane covers floats [4*lane, 4*lane+4)
    float4 q = *(const float4*)(g_Q + (size_t)d * DIMH + lane * 4);

    const int h = lane >> 2;          // head owning this lane's columns
    float ssum = 0.0f;                // per-head denominator (same in 4-lane group)

    // ---- Loop 1: scores -> ex -> denominator ----
    for (int p = beg; p < end; p++) {
        int src = g_ssrc[p];
        int eid = g_seid[p];
        float4 k = *(const float4*)(g_K + (size_t)src * DIMH + lane * 4);
        float dp = q.x * k.x + q.y * k.y + q.z * k.z + q.w * k.w;
        dp += __shfl_xor_sync(0xffffffffu, dp, 1);
        dp += __shfl_xor_sync(0xffffffffu, dp, 2);
        float bias = __ldg(ebias + (size_t)eid * NHEADS + h);
        float ex = __expf(dp * 0.25f + bias);
        ssum += ex;
        // lanes 0..7 write the 8 head values contiguously
        float exh = __shfl_sync(0xffffffffu, ex, (lane & 7) * 4);
        if (lane < NHEADS) g_ex[(size_t)p * NHEADS + lane] = exh;
    }

    float inv = 1.0f / ssum;                                   // per-head inverse
    float invh = __shfl_sync(0xffffffffu, inv, (lane & 7) * 4); // head l for lane l<8

    // ---- Loop 2: alpha, aggregate V, write alpha ----
    float4 acc = make_float4(0.f, 0.f, 0.f, 0.f);
    for (int p = beg; p < end; p++) {
        int src = g_ssrc[p];
        float ex = g_ex[(size_t)p * NHEADS + h];
        float alpha = ex * inv;
        float4 v = *(const float4*)(g_V + (size_t)src * DIMH + lane * 4);
        acc.x += alpha * v.x;
        acc.y += alpha * v.y;
        acc.z += alpha * v.z;
        acc.w += alpha * v.w;
        if (lane < NHEADS) {
            int eid = g_seid[p];
            out_alpha[(size_t)eid * NHEADS + lane] =
                g_ex[(size_t)p * NHEADS + lane] * invh;
        }
    }

    *(float4*)(out_h + (size_t)d * DIMH + lane * 4) = acc;
}

// ---------------------------------------------------------------------------
// Launch
// ---------------------------------------------------------------------------
extern "C" void kernel_launch(void* const* d_in, const int* in_sizes, int n_in,
                              void* d_out, int out_size) {
    const float* x     = (const float*)d_in[0];
    const int*   ei    = (const int*)d_in[1];
    const float* ebias = (const float*)d_in[2];
    const float* WQ    = (const float*)d_in[3];
    const float* bQ    = (const float*)d_in[4];
    const float* WK    = (const float*)d_in[5];
    const float* bK    = (const float*)d_in[6];
    const float* WV    = (const float*)d_in[7];
    const float* bV    = (const float*)d_in[8];

    int n = in_sizes[0] / DIMH;     // 50000
    int e = in_sizes[1] / 2;        // 800000

    float* out_h = (float*)d_out;
    float* out_alpha = out_h + (size_t)n * DIMH;

    // --- counting sort by dst -> CSR ---
    k_zero_counts<<<(n + 255) / 256, 256>>>(n);
    k_hist<<<(e + 255) / 256, 256>>>(ei, e);
    k_scan<<<1, 1024>>>(n);
    k_scatter<<<(e + 255) / 256, 256>>>(ei, e);

    // --- QKV projections (tf32 mma.sync) ---
    {
        dim3 grid((n + 127) / 128, 3);
        gemm_qkv_mma<<<grid, 256>>>(x, WQ, bQ, WK, bK, WV, bV, n);
    }

    // --- CSR attention: warp per destination node ---
    {
        long long threads = (long long)n * 32;
        int blocks = (int)((threads + 255) / 256);
        csr_edge<<<blocks, 256>>>(ebias, n, out_h, out_alpha);
    }
}